// round 5
// baseline (speedup 1.0000x reference)
#include <cuda_runtime.h>
#include <math.h>

#define VOCAB   128000
#define NVEC    (VOCAB / 4)
#define ROWB    (VOCAB * 4)          // 512000 bytes per row
#define TOPK    50
#define TOPP    0.9f
#define NEGV    (-1000000000.0f)
#define NBINS   4096
#define NCHUNK  (NBINS / 32)
#define CAP     4096
#define NT      1024
#define SSTRIDE 64
#define NSAMP   (VOCAB / SSTRIDE)   // 2000 samples per row
#define SCUM    8u
#define NEGCHUNK 16000               // bytes per bulk store (multiple of 16)
#define NCOPIES  (ROWB / NEGCHUNK)   // 32

__device__ __forceinline__ unsigned int fkey(float f) {
    unsigned int u = __float_as_uint(f);
    return (u & 0x80000000u) ? ~u : (u | 0x80000000u);
}
__device__ __forceinline__ float unkey(unsigned int k) {
    return __uint_as_float((k & 0x80000000u) ? (k & 0x7FFFFFFFu) : ~k);
}
__device__ __forceinline__ unsigned int smem_u32(const void* p) {
    unsigned int a;
    asm("{ .reg .u64 t; cvta.to.shared.u64 t, %1; cvt.u32.u64 %0, t; }" : "=r"(a) : "l"(p));
    return a;
}

__global__ __launch_bounds__(NT, 2)
void topk_topp_kernel(const float* __restrict__ logits, float* __restrict__ out) {
    __shared__ float negbuf[NEGCHUNK / 4];
    __shared__ unsigned int hist[NBINS];
    __shared__ unsigned int chunkSum[NCHUNK];
    __shared__ unsigned long long buf[CAP];   // (key<<32) | (0xFFFFFFFF - idx)
    __shared__ unsigned int s_cnt;
    __shared__ unsigned int s_thr;
    __shared__ unsigned int s_cntAbove;
    __shared__ int s_needRefine;
    __shared__ int s_m;

    const int row = blockIdx.x;
    const float* rp = logits + (size_t)row * VOCAB;
    const float4* rp4 = (const float4*)rp;
    float* op = out + (size_t)row * VOCAB;
    const int tid = threadIdx.x;

    // ---------------- init: NEG tile + hist ----------------
    for (int i = tid; i < NEGCHUNK / 4; i += NT) negbuf[i] = NEGV;
    for (int i = tid; i < NBINS; i += NT) hist[i] = 0u;
    if (tid == 0) s_cnt = 0u;
    __syncthreads();

    // ------- launch background NEG-fill of the whole output row (bulk async stores) -------
    if (tid == 0) {
        asm volatile("fence.proxy.async.shared::cta;" ::: "memory");
        unsigned int src = smem_u32(negbuf);
        char* dst = (char*)op;
        #pragma unroll 4
        for (int c = 0; c < NCOPIES; c++) {
            asm volatile("cp.async.bulk.global.shared::cta.bulk_group [%0], [%1], %2;"
                         :: "l"(dst + (size_t)c * NEGCHUNK), "r"(src), "n"(NEGCHUNK) : "memory");
        }
        asm volatile("cp.async.bulk.commit_group;" ::: "memory");
    }

    // ---------------- phase 0: sampled threshold estimate ----------------
    {
        float a = rp[tid * SSTRIDE];
        int j = tid + NT;
        float b = rp[(j < NSAMP ? j : tid) * SSTRIDE];
        atomicAdd(&hist[fkey(a) >> 20], 1u);
        if (j < NSAMP) atomicAdd(&hist[fkey(b) >> 20], 1u);
    }
    __syncthreads();
    if (tid < NCHUNK) {
        unsigned int s = 0;
        #pragma unroll 8
        for (int j = 0; j < 32; j++) s += hist[tid * 32 + j];
        chunkSum[tid] = s;
    }
    __syncthreads();
    if (tid == 0) {
        unsigned int cum = 0; int b = 0;
        for (int c = NCHUNK - 1; c >= 0; c--) {
            if (cum + chunkSum[c] >= SCUM) {
                for (int j = 31; j >= 0; j--) {
                    int bin = c * 32 + j; cum += hist[bin];
                    if (cum >= SCUM) { b = bin; break; }
                }
                break;
            }
            cum += chunkSum[c];
        }
        s_thr = ((unsigned int)b) << 20;
    }
    __syncthreads();

    // ---------------- phase 1: pure-read candidate collection ----------------
    {
        const unsigned int T = s_thr;
        for (int i = tid; i < NVEC; i += NT) {
            float4 v = rp4[i];
            unsigned int k0 = fkey(v.x), k1 = fkey(v.y), k2 = fkey(v.z), k3 = fkey(v.w);
            unsigned int g = (unsigned int)(i * 4);
            if (k0 >= T) { unsigned p = atomicAdd(&s_cnt, 1u); if (p < CAP) buf[p] = ((unsigned long long)k0 << 32) | (unsigned long long)(0xFFFFFFFFu - g); }
            if (k1 >= T) { unsigned p = atomicAdd(&s_cnt, 1u); if (p < CAP) buf[p] = ((unsigned long long)k1 << 32) | (unsigned long long)(0xFFFFFFFFu - (g + 1u)); }
            if (k2 >= T) { unsigned p = atomicAdd(&s_cnt, 1u); if (p < CAP) buf[p] = ((unsigned long long)k2 << 32) | (unsigned long long)(0xFFFFFFFFu - (g + 2u)); }
            if (k3 >= T) { unsigned p = atomicAdd(&s_cnt, 1u); if (p < CAP) buf[p] = ((unsigned long long)k3 << 32) | (unsigned long long)(0xFFFFFFFFu - (g + 3u)); }
        }
    }
    __syncthreads();

    // ------- phase 1b: exact fallback if sampling mis-estimated (rare) -------
    if (s_cnt < (unsigned)TOPK || s_cnt > (unsigned)CAP) {
        for (int i = tid; i < NBINS; i += NT) hist[i] = 0u;
        __syncthreads();
        for (int i = tid; i < NVEC; i += NT) {
            float4 v = rp4[i];
            atomicAdd(&hist[fkey(v.x) >> 20], 1u);
            atomicAdd(&hist[fkey(v.y) >> 20], 1u);
            atomicAdd(&hist[fkey(v.z) >> 20], 1u);
            atomicAdd(&hist[fkey(v.w) >> 20], 1u);
        }
        __syncthreads();
        if (tid < NCHUNK) {
            unsigned int s = 0;
            #pragma unroll 8
            for (int j = 0; j < 32; j++) s += hist[tid * 32 + j];
            chunkSum[tid] = s;
        }
        __syncthreads();
        if (tid == 0) {
            unsigned int cum = 0; int b = 0;
            for (int c = NCHUNK - 1; c >= 0; c--) {
                if (cum + chunkSum[c] >= (unsigned)TOPK) {
                    for (int j = 31; j >= 0; j--) {
                        int bin = c * 32 + j; cum += hist[bin];
                        if (cum >= (unsigned)TOPK) { b = bin; break; }
                    }
                    break;
                }
                cum += chunkSum[c];
            }
            s_cntAbove = cum - hist[b];
            s_needRefine = (cum > (unsigned)CAP) ? 1 : 0;
            s_thr = ((unsigned int)b) << 20;
            s_cnt = 0u;
        }
        __syncthreads();
        if (s_needRefine) {
            const unsigned int bb = s_thr >> 20;
            const unsigned int above = s_cntAbove;
            for (int i = tid; i < NBINS; i += NT) hist[i] = 0u;
            __syncthreads();
            for (int i = tid; i < NVEC; i += NT) {
                float4 v = rp4[i];
                unsigned int k0 = fkey(v.x), k1 = fkey(v.y), k2 = fkey(v.z), k3 = fkey(v.w);
                if ((k0 >> 20) == bb) atomicAdd(&hist[(k0 >> 8) & 0xFFFu], 1u);
                if ((k1 >> 20) == bb) atomicAdd(&hist[(k1 >> 8) & 0xFFFu], 1u);
                if ((k2 >> 20) == bb) atomicAdd(&hist[(k2 >> 8) & 0xFFFu], 1u);
                if ((k3 >> 20) == bb) atomicAdd(&hist[(k3 >> 8) & 0xFFFu], 1u);
            }
            __syncthreads();
            if (tid < NCHUNK) {
                unsigned int s = 0;
                #pragma unroll 8
                for (int j = 0; j < 32; j++) s += hist[tid * 32 + j];
                chunkSum[tid] = s;
            }
            __syncthreads();
            if (tid == 0) {
                unsigned int cum = above; int b2 = 0;
                for (int c = NCHUNK - 1; c >= 0; c--) {
                    if (cum + chunkSum[c] >= (unsigned)TOPK) {
                        for (int j = 31; j >= 0; j--) {
                            int bin = c * 32 + j; cum += hist[bin];
                            if (cum >= (unsigned)TOPK) { b2 = bin; break; }
                        }
                        break;
                    }
                    cum += chunkSum[c];
                }
                s_thr = (bb << 20) | (((unsigned int)b2) << 8);
                s_cnt = 0u;
            }
            __syncthreads();
        }
        {
            const unsigned int T = s_thr;
            const int refine = s_needRefine;
            for (int i = tid; i < NVEC; i += NT) {
                float4 v = rp4[i];
                unsigned int k[4] = {fkey(v.x), fkey(v.y), fkey(v.z), fkey(v.w)};
                unsigned int g = (unsigned int)(i * 4);
                #pragma unroll
                for (int c = 0; c < 4; c++) {
                    unsigned int kc = k[c];
                    bool pass = refine ? ((kc >> 8) >= (T >> 8)) : (kc >= T);
                    if (pass) {
                        unsigned p = atomicAdd(&s_cnt, 1u);
                        if (p < CAP) buf[p] = ((unsigned long long)kc << 32) | (unsigned long long)(0xFFFFFFFFu - (g + (unsigned)c));
                    }
                }
            }
        }
        __syncthreads();
    }

    // ---------------- phase 2: sort candidates (desc value, asc index) ----------------
    int C = (int)min(s_cnt, (unsigned)CAP);
    int N2 = 64; while (N2 < C) N2 <<= 1;
    for (int i = C + tid; i < N2; i += NT) buf[i] = 0ULL;
    __syncthreads();
    for (unsigned int k = 2; k <= (unsigned)N2; k <<= 1) {
        for (unsigned int j = k >> 1; j > 0; j >>= 1) {
            for (unsigned int i = tid; i < (unsigned)N2; i += NT) {
                unsigned int ixj = i ^ j;
                if (ixj > i) {
                    unsigned long long a = buf[i], c = buf[ixj];
                    bool up = ((i & k) == 0u);
                    if (up ? (a < c) : (a > c)) { buf[i] = c; buf[ixj] = a; }
                }
            }
            __syncthreads();
        }
    }

    // ---------------- phase 3: top-p over sorted top-50; ensure NEG fill done ----------------
    if (tid == 0) {
        asm volatile("cp.async.bulk.wait_group 0;" ::: "memory");
        int kk = (C < TOPK) ? C : TOPK;
        float vmax = unkey((unsigned int)(buf[0] >> 32));
        float e[TOPK];
        float s = 0.0f;
        for (int i = 0; i < kk; i++) {
            e[i] = expf(unkey((unsigned int)(buf[i] >> 32)) - vmax);
            s += e[i];
        }
        float cum = 0.0f;
        int m = kk;
        for (int i = 0; i < kk; i++) {
            cum += e[i] / s;
            if (cum > TOPP) { m = i + 1; break; }
        }
        s_m = m;
    }
    __syncthreads();

    // ---------------- phase 4: scatter kept values ----------------
    if (tid < s_m) {
        unsigned long long b = buf[tid];
        unsigned int g = 0xFFFFFFFFu - (unsigned int)(b & 0xFFFFFFFFu);
        op[g] = unkey((unsigned int)(b >> 32));
    }
}

extern "C" void kernel_launch(void* const* d_in, const int* in_sizes, int n_in,
                              void* d_out, int out_size) {
    const float* logits = (const float*)d_in[0];
    float* out = (float*)d_out;
    int rows = in_sizes[0] / VOCAB;          // 256
    topk_topp_kernel<<<rows, NT>>>(logits, out);
}

// round 6
// speedup vs baseline: 1.6260x; 1.6260x over previous
#include <cuda_runtime.h>
#include <math.h>

#define VOCAB   128000
#define NVEC    (VOCAB / 4)
#define TOPK    50
#define TOPP    0.9f
#define NEGV    (-1000000000.0f)
#define NBINS   4096
#define NCHUNK  (NBINS / 32)
#define CAP     2048
#define ROWSMAX 256
#define SEGS    8
#define VPSEG   (NVEC / SEGS)     // 4000 float4 per segment
#define K1NT    256
#define K2NT    256
#define THRVAL  3.0f              // fixed candidate threshold (fallback covers misses)

__device__ unsigned int g_cnt[ROWSMAX];
__device__ unsigned long long g_buf[ROWSMAX * CAP];

__device__ __forceinline__ unsigned int fkey(float f) {
    unsigned int u = __float_as_uint(f);
    return (u & 0x80000000u) ? ~u : (u | 0x80000000u);
}
__device__ __forceinline__ float unkey(unsigned int k) {
    return __uint_as_float((k & 0x80000000u) ? (k & 0x7FFFFFFFu) : ~k);
}

// ---------------- K1: stream read + NEG-fill + smem candidate collect ----------------
__global__ __launch_bounds__(K1NT)
void k1_stream(const float* __restrict__ logits, float* __restrict__ out) {
    __shared__ unsigned long long lbuf[CAP];
    __shared__ unsigned int s_c;
    __shared__ unsigned int s_base;

    const int row = blockIdx.y;
    const int seg = blockIdx.x;
    const float4* rp4 = (const float4*)(logits + (size_t)row * VOCAB);
    float4* op4 = (float4*)(out + (size_t)row * VOCAB);
    const int tid = threadIdx.x;
    if (tid == 0) s_c = 0u;
    __syncthreads();

    const unsigned int T = fkey(THRVAL);
    const float4 neg4 = make_float4(NEGV, NEGV, NEGV, NEGV);
    const int base = seg * VPSEG;
    const int end = base + VPSEG;

    for (int i = base + tid; i < end; i += K1NT) {
        float4 v = rp4[i];
        op4[i] = neg4;
        unsigned int k0 = fkey(v.x), k1 = fkey(v.y), k2 = fkey(v.z), k3 = fkey(v.w);
        unsigned int g = (unsigned int)(i * 4);
        if (k0 >= T) { unsigned p = atomicAdd(&s_c, 1u); if (p < CAP) lbuf[p] = ((unsigned long long)k0 << 32) | (unsigned long long)(0xFFFFFFFFu - g); }
        if (k1 >= T) { unsigned p = atomicAdd(&s_c, 1u); if (p < CAP) lbuf[p] = ((unsigned long long)k1 << 32) | (unsigned long long)(0xFFFFFFFFu - (g + 1u)); }
        if (k2 >= T) { unsigned p = atomicAdd(&s_c, 1u); if (p < CAP) lbuf[p] = ((unsigned long long)k2 << 32) | (unsigned long long)(0xFFFFFFFFu - (g + 2u)); }
        if (k3 >= T) { unsigned p = atomicAdd(&s_c, 1u); if (p < CAP) lbuf[p] = ((unsigned long long)k3 << 32) | (unsigned long long)(0xFFFFFFFFu - (g + 3u)); }
    }
    __syncthreads();

    const unsigned int cnt = s_c;                     // true attempted count
    const unsigned int stored = cnt < CAP ? cnt : CAP;
    if (tid == 0) s_base = atomicAdd(&g_cnt[row], cnt);   // one global atomic per CTA
    __syncthreads();
    const unsigned int b0 = s_base;
    unsigned long long* gb = &g_buf[(size_t)row * CAP];
    for (unsigned int i = tid; i < stored; i += K1NT) {
        unsigned int p = b0 + i;
        if (p < CAP) gb[p] = lbuf[i];
    }
}

// ---------------- K2: per-row finalize ----------------
__global__ __launch_bounds__(K2NT)
void k2_finalize(const float* __restrict__ logits, float* __restrict__ out) {
    __shared__ unsigned long long buf[CAP];
    __shared__ unsigned int hist[NBINS];
    __shared__ unsigned int chunkSum[NCHUNK];
    __shared__ unsigned int s_cnt;
    __shared__ unsigned int s_thr;
    __shared__ unsigned int s_cntAbove;
    __shared__ int s_needRefine;
    __shared__ int s_m;

    const int row = blockIdx.x;
    const float4* rp4 = (const float4*)(logits + (size_t)row * VOCAB);
    const int tid = threadIdx.x;

    const unsigned int cnt = g_cnt[row];
    if (tid == 0) g_cnt[row] = 0u;    // reset for next graph replay
    int C;

    if (cnt >= (unsigned)TOPK && cnt <= (unsigned)CAP) {
        // fast path: copy candidates to smem
        C = (int)cnt;
        const unsigned long long* gb = &g_buf[(size_t)row * CAP];
        for (int i = tid; i < C; i += K2NT) buf[i] = gb[i];
        __syncthreads();
    } else {
        // -------- exact fallback: histogram select + re-collect (rare) --------
        for (int i = tid; i < NBINS; i += K2NT) hist[i] = 0u;
        __syncthreads();
        for (int i = tid; i < NVEC; i += K2NT) {
            float4 v = rp4[i];
            atomicAdd(&hist[fkey(v.x) >> 20], 1u);
            atomicAdd(&hist[fkey(v.y) >> 20], 1u);
            atomicAdd(&hist[fkey(v.z) >> 20], 1u);
            atomicAdd(&hist[fkey(v.w) >> 20], 1u);
        }
        __syncthreads();
        if (tid < NCHUNK) {
            unsigned int s = 0;
            #pragma unroll 8
            for (int j = 0; j < 32; j++) s += hist[tid * 32 + j];
            chunkSum[tid] = s;
        }
        __syncthreads();
        if (tid == 0) {
            unsigned int cum = 0; int b = 0;
            for (int c = NCHUNK - 1; c >= 0; c--) {
                if (cum + chunkSum[c] >= (unsigned)TOPK) {
                    for (int j = 31; j >= 0; j--) {
                        int bin = c * 32 + j; cum += hist[bin];
                        if (cum >= (unsigned)TOPK) { b = bin; break; }
                    }
                    break;
                }
                cum += chunkSum[c];
            }
            s_cntAbove = cum - hist[b];
            s_needRefine = (cum > (unsigned)CAP) ? 1 : 0;
            s_thr = ((unsigned int)b) << 20;
            s_cnt = 0u;
        }
        __syncthreads();
        if (s_needRefine) {
            const unsigned int bb = s_thr >> 20;
            const unsigned int above = s_cntAbove;
            for (int i = tid; i < NBINS; i += K2NT) hist[i] = 0u;
            __syncthreads();
            for (int i = tid; i < NVEC; i += K2NT) {
                float4 v = rp4[i];
                unsigned int k0 = fkey(v.x), k1 = fkey(v.y), k2 = fkey(v.z), k3 = fkey(v.w);
                if ((k0 >> 20) == bb) atomicAdd(&hist[(k0 >> 8) & 0xFFFu], 1u);
                if ((k1 >> 20) == bb) atomicAdd(&hist[(k1 >> 8) & 0xFFFu], 1u);
                if ((k2 >> 20) == bb) atomicAdd(&hist[(k2 >> 8) & 0xFFFu], 1u);
                if ((k3 >> 20) == bb) atomicAdd(&hist[(k3 >> 8) & 0xFFFu], 1u);
            }
            __syncthreads();
            if (tid < NCHUNK) {
                unsigned int s = 0;
                #pragma unroll 8
                for (int j = 0; j < 32; j++) s += hist[tid * 32 + j];
                chunkSum[tid] = s;
            }
            __syncthreads();
            if (tid == 0) {
                unsigned int cum = above; int b2 = 0;
                for (int c = NCHUNK - 1; c >= 0; c--) {
                    if (cum + chunkSum[c] >= (unsigned)TOPK) {
                        for (int j = 31; j >= 0; j--) {
                            int bin = c * 32 + j; cum += hist[bin];
                            if (cum >= (unsigned)TOPK) { b2 = bin; break; }
                        }
                        break;
                    }
                    cum += chunkSum[c];
                }
                s_thr = (bb << 20) | (((unsigned int)b2) << 8);
                s_cnt = 0u;
            }
            __syncthreads();
        }
        {
            const unsigned int T = s_thr;
            const int refine = s_needRefine;
            for (int i = tid; i < NVEC; i += K2NT) {
                float4 v = rp4[i];
                unsigned int k[4] = {fkey(v.x), fkey(v.y), fkey(v.z), fkey(v.w)};
                unsigned int g = (unsigned int)(i * 4);
                #pragma unroll
                for (int c = 0; c < 4; c++) {
                    unsigned int kc = k[c];
                    bool pass = refine ? ((kc >> 8) >= (T >> 8)) : (kc >= T);
                    if (pass) {
                        unsigned p = atomicAdd(&s_cnt, 1u);
                        if (p < CAP) buf[p] = ((unsigned long long)kc << 32) | (unsigned long long)(0xFFFFFFFFu - (g + (unsigned)c));
                    }
                }
            }
        }
        __syncthreads();
        C = (int)min(s_cnt, (unsigned)CAP);
    }

    // -------- bitonic sort (desc value, asc index) --------
    int N2 = 64; while (N2 < C) N2 <<= 1;
    for (int i = C + tid; i < N2; i += K2NT) buf[i] = 0ULL;
    __syncthreads();
    for (unsigned int k = 2; k <= (unsigned)N2; k <<= 1) {
        for (unsigned int j = k >> 1; j > 0; j >>= 1) {
            for (unsigned int i = tid; i < (unsigned)N2; i += K2NT) {
                unsigned int ixj = i ^ j;
                if (ixj > i) {
                    unsigned long long a = buf[i], c = buf[ixj];
                    bool up = ((i & k) == 0u);
                    if (up ? (a < c) : (a > c)) { buf[i] = c; buf[ixj] = a; }
                }
            }
            __syncthreads();
        }
    }

    // -------- top-p over sorted top-50 --------
    if (tid == 0) {
        int kk = (C < TOPK) ? C : TOPK;
        float vmax = unkey((unsigned int)(buf[0] >> 32));
        float e[TOPK];
        float s = 0.0f;
        for (int i = 0; i < kk; i++) {
            e[i] = expf(unkey((unsigned int)(buf[i] >> 32)) - vmax);
            s += e[i];
        }
        float cum = 0.0f;
        int m = kk;
        for (int i = 0; i < kk; i++) {
            cum += e[i] / s;
            if (cum > TOPP) { m = i + 1; break; }
        }
        s_m = m;
    }
    __syncthreads();

    // -------- scatter kept values --------
    if (tid < s_m) {
        unsigned long long b = buf[tid];
        unsigned int g = 0xFFFFFFFFu - (unsigned int)(b & 0xFFFFFFFFu);
        out[(size_t)row * VOCAB + g] = unkey((unsigned int)(b >> 32));
    }
}

extern "C" void kernel_launch(void* const* d_in, const int* in_sizes, int n_in,
                              void* d_out, int out_size) {
    const float* logits = (const float*)d_in[0];
    float* out = (float*)d_out;
    int rows = in_sizes[0] / VOCAB;          // 256
    dim3 g1(SEGS, rows);
    k1_stream<<<g1, K1NT>>>(logits, out);
    k2_finalize<<<rows, K2NT>>>(logits, out);
}